// round 4
// baseline (speedup 1.0000x reference)
#include <cuda_runtime.h>
#include <cuda_bf16.h>
#include <math.h>

#define T     1024
#define HDIM  1024
#define NEXP  16
#define IDIM  512
#define ISDIM 2048
#define TOPK  4

// ---------------- scratch --------------------------------------------------
__device__ int   g_counts[NEXP];
__device__ int   g_tok[NEXP * T];
__device__ float g_wt[NEXP * T];
__device__ int   g_slot[T * TOPK];
__device__ float g_sg[T];
__device__ float g_act[(size_t)NEXP * T * IDIM];
__device__ float g_acts[(size_t)T * ISDIM];
__device__ float g_down[(size_t)NEXP * T * HDIM];

// ---------------- helpers --------------------------------------------------
__device__ __forceinline__ float to_tf32(float x) {
    unsigned u;
    asm("cvt.rna.tf32.f32 %0, %1;" : "=r"(u) : "f"(x));
    return __uint_as_float(u);
}
__device__ __forceinline__ void mma_tf32(float* d, const float* a, const float* b) {
    asm volatile(
        "mma.sync.aligned.m16n8k8.row.col.f32.tf32.tf32.f32 "
        "{%0,%1,%2,%3}, {%4,%5,%6,%7}, {%8,%9}, {%0,%1,%2,%3};\n"
        : "+f"(d[0]), "+f"(d[1]), "+f"(d[2]), "+f"(d[3])
        : "r"(__float_as_uint(a[0])), "r"(__float_as_uint(a[1])),
          "r"(__float_as_uint(a[2])), "r"(__float_as_uint(a[3])),
          "r"(__float_as_uint(b[0])), "r"(__float_as_uint(b[1])));
}
__device__ __forceinline__ float silu(float g) { return g / (1.f + expf(-g)); }

// Fragment-order smem stores. BK=16 (kb in {0,1}).
// A layout: [kb][mt(4)][lane(32)][reg(4)]  (1024 floats / buffer)
// B layout: [kb][nt(NT)][lane(32)][reg(2)] (NT*128 floats / buffer)
__device__ __forceinline__ void sts_a(float* As, int row, int k0, float4 v) {
    // row in [0,64), k0 multiple of 4 in [0,16)
    int kb = k0 >> 3, hk = (k0 >> 2) & 1;
    int mt = row >> 4, rm = row & 15;
    int reg = (rm >> 3) + 2 * hk, rp = rm & 7;
    int base = ((kb * 4 + mt) * 32 + rp * 4) * 4 + reg;
    As[base]      = to_tf32(v.x);
    As[base + 4]  = to_tf32(v.y);
    As[base + 8]  = to_tf32(v.z);
    As[base + 12] = to_tf32(v.w);
}
template <int NT>
__device__ __forceinline__ void sts_b(float* Bs, int kk, int n0, float4 v) {
    // kk in [0,16), n0 multiple of 4
    int kb = kk >> 3, reg = (kk >> 2) & 1, cp = kk & 3;
    int nt = n0 >> 3, nb = n0 & 7;
    int base = ((kb * NT + nt) * 32 + nb * 4 + cp) * 2 + reg;
    Bs[base]      = to_tf32(v.x);
    Bs[base + 8]  = to_tf32(v.y);
    Bs[base + 16] = to_tf32(v.z);
    Bs[base + 24] = to_tf32(v.w);
}

// ---------------- kernel 0 + 1: counts & router -----------------------------
__global__ void zero_counts_kernel() {
    if (threadIdx.x < NEXP) g_counts[threadIdx.x] = 0;
}

__global__ void router_kernel(const float* __restrict__ x,
                              const float* __restrict__ wr,
                              const float* __restrict__ wsg,
                              float* __restrict__ logits_out) {
    int t    = blockIdx.x;
    int warp = threadIdx.x >> 5;
    int lane = threadIdx.x & 31;
    __shared__ float s_logit[NEXP];

    const float* xr = x + (size_t)t * HDIM;
    {
        float acc = 0.f;
        for (int h = lane; h < HDIM; h += 32)
            acc += xr[h] * wr[h * NEXP + warp];
        #pragma unroll
        for (int o = 16; o; o >>= 1) acc += __shfl_xor_sync(0xffffffffu, acc, o);
        if (lane == 0) { s_logit[warp] = acc; logits_out[t * NEXP + warp] = acc; }
    }
    if (warp == 0) {
        float acc = 0.f;
        for (int h = lane; h < HDIM; h += 32) acc += xr[h] * wsg[h];
        #pragma unroll
        for (int o = 16; o; o >>= 1) acc += __shfl_xor_sync(0xffffffffu, acc, o);
        if (lane == 0) g_sg[t] = 1.f / (1.f + expf(-acc));
    }
    __syncthreads();

    if (threadIdx.x == 0) {
        float p[NEXP];
        float mx = -1e30f;
        #pragma unroll
        for (int e = 0; e < NEXP; e++) mx = fmaxf(mx, s_logit[e]);
        float sum = 0.f;
        #pragma unroll
        for (int e = 0; e < NEXP; e++) { p[e] = expf(s_logit[e] - mx); sum += p[e]; }
        float inv = 1.f / sum;
        #pragma unroll
        for (int e = 0; e < NEXP; e++) p[e] *= inv;

        int idx[TOPK]; float w[TOPK]; float wsum = 0.f;
        #pragma unroll
        for (int k = 0; k < TOPK; k++) {
            int best = 0; float bv = -1.f;
            #pragma unroll
            for (int e = 0; e < NEXP; e++)
                if (p[e] > bv) { bv = p[e]; best = e; }
            idx[k] = best; w[k] = bv; wsum += bv; p[best] = -2.f;
        }
        float winv = 1.f / wsum;
        #pragma unroll
        for (int k = 0; k < TOPK; k++) {
            int e = idx[k];
            int pos = atomicAdd(&g_counts[e], 1);
            g_tok[e * T + pos] = t;
            g_wt[e * T + pos]  = w[k] * winv;
            g_slot[t * TOPK + k] = e * T + pos;
        }
    }
}

// ============================================================================
// gate/up kernels: BM=64, BN=64, BK=16, 128 thr, 4 warps 2x2 (warp 32x32),
// one A-fragment feeds both gate and up MMAs.
// ============================================================================
__global__ __launch_bounds__(128)
void gateup_expert_tc(const float* __restrict__ x,
                      const float* __restrict__ wg,
                      const float* __restrict__ wu) {
    int e     = blockIdx.z;
    int count = g_counts[e];
    int m0    = blockIdx.y * 64;
    if (m0 >= count) return;
    int n0 = blockIdx.x * 64;

    const float* Bgp = wg + (size_t)e * HDIM * IDIM;
    const float* Bup = wu + (size_t)e * HDIM * IDIM;

    __shared__ float As[2][1024];
    __shared__ float Bgs[2][1024];
    __shared__ float Bus[2][1024];

    int tid = threadIdx.x, lane = tid & 31, warp = tid >> 5;
    int wmt = (warp >> 1) * 2, wnt = (warp & 1) * 4;
    int r = lane >> 2, c = lane & 3;

    int ar = tid >> 1, ak = (tid & 1) * 8;        // A loader: row, k-half
    int br = tid >> 3, bc = (tid & 7) * 8;        // B loader: k-row, n-group

    int row = m0 + ar;
    const float* arow = (row < count) ? (x + (size_t)g_tok[e * T + row] * HDIM)
                                      : nullptr;

    float4 pa0, pa1, pg0, pg1, pu0, pu1;
    #define GU_LD(K0) do {                                                       \
        pa0 = arow ? *(const float4*)(arow + (K0) + ak) : make_float4(0,0,0,0);  \
        pa1 = arow ? *(const float4*)(arow + (K0) + ak + 4) : make_float4(0,0,0,0);\
        pg0 = *(const float4*)(Bgp + (size_t)((K0) + br) * IDIM + n0 + bc);      \
        pg1 = *(const float4*)(Bgp + (size_t)((K0) + br) * IDIM + n0 + bc + 4);  \
        pu0 = *(const float4*)(Bup + (size_t)((K0) + br) * IDIM + n0 + bc);      \
        pu1 = *(const float4*)(Bup + (size_t)((K0) + br) * IDIM + n0 + bc + 4);  \
    } while (0)
    #define GU_ST(B) do {                                                        \
        sts_a(As[B], ar, ak, pa0);     sts_a(As[B], ar, ak + 4, pa1);            \
        sts_b<8>(Bgs[B], br, bc, pg0); sts_b<8>(Bgs[B], br, bc + 4, pg1);        \
        sts_b<8>(Bus[B], br, bc, pu0); sts_b<8>(Bus[B], br, bc + 4, pu1);        \
    } while (0)

    float ag[2][4][4] = {};
    float au[2][4][4] = {};

    GU_LD(0); GU_ST(0);
    const int NTILES = HDIM / 16;
    for (int kt = 0; kt < NTILES; kt++) {
        __syncthreads();
        if (kt + 1 < NTILES) GU_LD((kt + 1) * 16);
        int b = kt & 1;
        #pragma unroll
        for (int kb = 0; kb < 2; kb++) {
            float4 afr[2];
            #pragma unroll
            for (int mt = 0; mt < 2; mt++)
                afr[mt] = *(const float4*)&As[b][((kb * 4 + wmt + mt) * 32 + lane) * 4];
            float2 bg[4], bu[4];
            #pragma unroll
            for (int nt = 0; nt < 4; nt++) {
                bg[nt] = *(const float2*)&Bgs[b][((kb * 8 + wnt + nt) * 32 + lane) * 2];
                bu[nt] = *(const float2*)&Bus[b][((kb * 8 + wnt + nt) * 32 + lane) * 2];
            }
            #pragma unroll
            for (int nt = 0; nt < 4; nt++)
                #pragma unroll
                for (int mt = 0; mt < 2; mt++) {
                    mma_tf32(ag[mt][nt], (const float*)&afr[mt], (const float*)&bg[nt]);
                    mma_tf32(au[mt][nt], (const float*)&afr[mt], (const float*)&bu[nt]);
                }
        }
        if (kt + 1 < NTILES) GU_ST((kt + 1) & 1);
    }

    float* Cb = g_act + (size_t)e * T * IDIM;
    #pragma unroll
    for (int mt = 0; mt < 2; mt++) {
        int row0 = m0 + (wmt + mt) * 16 + r;
        #pragma unroll
        for (int nt = 0; nt < 4; nt++) {
            int col = n0 + (wnt + nt) * 8 + c * 2;
            if (row0 < count) {
                float2 o = { silu(ag[mt][nt][0]) * au[mt][nt][0],
                             silu(ag[mt][nt][1]) * au[mt][nt][1] };
                *(float2*)(Cb + (size_t)row0 * IDIM + col) = o;
            }
            if (row0 + 8 < count) {
                float2 o = { silu(ag[mt][nt][2]) * au[mt][nt][2],
                             silu(ag[mt][nt][3]) * au[mt][nt][3] };
                *(float2*)(Cb + (size_t)(row0 + 8) * IDIM + col) = o;
            }
        }
    }
}

__global__ __launch_bounds__(128)
void gateup_shared_tc(const float* __restrict__ x,
                      const float* __restrict__ wsg,
                      const float* __restrict__ wsu) {
    int m0 = blockIdx.y * 64;
    int n0 = blockIdx.x * 64;

    __shared__ float As[2][1024];
    __shared__ float Bgs[2][1024];
    __shared__ float Bus[2][1024];

    int tid = threadIdx.x, lane = tid & 31, warp = tid >> 5;
    int wmt = (warp >> 1) * 2, wnt = (warp & 1) * 4;
    int r = lane >> 2, c = lane & 3;

    int ar = tid >> 1, ak = (tid & 1) * 8;
    int br = tid >> 3, bc = (tid & 7) * 8;

    const float* arow = x + (size_t)(m0 + ar) * HDIM;

    float4 pa0, pa1, pg0, pg1, pu0, pu1;
    #define GS_LD(K0) do {                                                       \
        pa0 = *(const float4*)(arow + (K0) + ak);                                \
        pa1 = *(const float4*)(arow + (K0) + ak + 4);                            \
        pg0 = *(const float4*)(wsg + (size_t)((K0) + br) * ISDIM + n0 + bc);     \
        pg1 = *(const float4*)(wsg + (size_t)((K0) + br) * ISDIM + n0 + bc + 4); \
        pu0 = *(const float4*)(wsu + (size_t)((K0) + br) * ISDIM + n0 + bc);     \
        pu1 = *(const float4*)(wsu + (size_t)((K0) + br) * ISDIM + n0 + bc + 4); \
    } while (0)

    float ag[2][4][4] = {};
    float au[2][4][4] = {};

    GS_LD(0); GU_ST(0);
    const int NTILES = HDIM / 16;
    for (int kt = 0; kt < NTILES; kt++) {
        __syncthreads();
        if (kt + 1 < NTILES) GS_LD((kt + 1) * 16);
        int b = kt & 1;
        #pragma unroll
        for (int kb = 0; kb < 2; kb++) {
            float4 afr[2];
            #pragma unroll
            for (int mt = 0; mt < 2; mt++)
                afr[mt] = *(const float4*)&As[b][((kb * 4 + wmt + mt) * 32 + lane) * 4];
            float2 bg[4], bu[4];
            #pragma unroll
            for (int nt = 0; nt < 4; nt++) {
                bg[nt] = *(const float2*)&Bgs[b][((kb * 8 + wnt + nt) * 32 + lane) * 2];
                bu[nt] = *(const float2*)&Bus[b][((kb * 8 + wnt + nt) * 32 + lane) * 2];
            }
            #pragma unroll
            for (int nt = 0; nt < 4; nt++)
                #pragma unroll
                for (int mt = 0; mt < 2; mt++) {
                    mma_tf32(ag[mt][nt], (const float*)&afr[mt], (const float*)&bg[nt]);
                    mma_tf32(au[mt][nt], (const float*)&afr[mt], (const float*)&bu[nt]);
                }
        }
        if (kt + 1 < NTILES) GU_ST((kt + 1) & 1);
    }

    #pragma unroll
    for (int mt = 0; mt < 2; mt++) {
        int row0 = m0 + (wmt + mt) * 16 + r;
        #pragma unroll
        for (int nt = 0; nt < 4; nt++) {
            int col = n0 + (wnt + nt) * 8 + c * 2;
            float2 o0 = { silu(ag[mt][nt][0]) * au[mt][nt][0],
                          silu(ag[mt][nt][1]) * au[mt][nt][1] };
            float2 o1 = { silu(ag[mt][nt][2]) * au[mt][nt][2],
                          silu(ag[mt][nt][3]) * au[mt][nt][3] };
            *(float2*)(g_acts + (size_t)row0 * ISDIM + col)       = o0;
            *(float2*)(g_acts + (size_t)(row0 + 8) * ISDIM + col) = o1;
        }
    }
}

// ============================================================================
// down kernels: BM=64, BN=128, BK=16, 128 thr, 4 warps 2x2 (warp 32x64).
// ============================================================================
__global__ __launch_bounds__(128)
void down_expert_tc(const float* __restrict__ wd) {
    int e     = blockIdx.z;
    int count = g_counts[e];
    int m0    = blockIdx.y * 64;
    if (m0 >= count) return;
    int n0 = blockIdx.x * 128;

    const float* A = g_act + (size_t)e * T * IDIM;
    const float* B = wd    + (size_t)e * IDIM * HDIM;

    __shared__ float As[2][1024];
    __shared__ float Bs[2][2048];

    int tid = threadIdx.x, lane = tid & 31, warp = tid >> 5;
    int wmt = (warp >> 1) * 2, wnt = (warp & 1) * 8;
    int r = lane >> 2, c = lane & 3;

    int ar = tid >> 1, ak = (tid & 1) * 8;
    int br = tid >> 3, bc = (tid & 7) * 16;

    const float* arow = A + (size_t)(m0 + ar) * IDIM;

    float4 pa0, pa1, pb[4];
    #define DN_LD(BP, LDB, K0) do {                                              \
        pa0 = *(const float4*)(arow + (K0) + ak);                                \
        pa1 = *(const float4*)(arow + (K0) + ak + 4);                            \
        _Pragma("unroll")                                                        \
        for (int i = 0; i < 4; i++)                                              \
            pb[i] = *(const float4*)((BP) + (size_t)((K0) + br) * (LDB)          \
                                     + n0 + bc + i * 4);                         \
    } while (0)
    #define DN_ST(BUF) do {                                                      \
        sts_a(As[BUF], ar, ak, pa0); sts_a(As[BUF], ar, ak + 4, pa1);            \
        _Pragma("unroll")                                                        \
        for (int i = 0; i < 4; i++) sts_b<16>(Bs[BUF], br, bc + i * 4, pb[i]);   \
    } while (0)

    float acc[2][8][4] = {};

    DN_LD(B, HDIM, 0); DN_ST(0);
    const int NTILES = IDIM / 16;
    for (int kt = 0; kt < NTILES; kt++) {
        __syncthreads();
        if (kt + 1 < NTILES) DN_LD(B, HDIM, (kt + 1) * 16);
        int b = kt & 1;
        #pragma unroll
        for (int kb = 0; kb < 2; kb++) {
            float4 afr[2];
            #pragma unroll
            for (int mt = 0; mt < 2; mt++)
                afr[mt] = *(const float4*)&As[b][((kb * 4 + wmt + mt) * 32 + lane) * 4];
            float2 bf[8];
            #pragma unroll
            for (int nt = 0; nt < 8; nt++)
                bf[nt] = *(const float2*)&Bs[b][((kb * 16 + wnt + nt) * 32 + lane) * 2];
            #pragma unroll
            for (int nt = 0; nt < 8; nt++)
                #pragma unroll
                for (int mt = 0; mt < 2; mt++)
                    mma_tf32(acc[mt][nt], (const float*)&afr[mt], (const float*)&bf[nt]);
        }
        if (kt + 1 < NTILES) DN_ST((kt + 1) & 1);
    }

    #pragma unroll
    for (int mt = 0; mt < 2; mt++) {
        int row0 = m0 + (wmt + mt) * 16 + r;
        float w0 = (row0 < count)     ? g_wt[e * T + row0]     : 0.f;
        float w1 = (row0 + 8 < count) ? g_wt[e * T + row0 + 8] : 0.f;
        #pragma unroll
        for (int nt = 0; nt < 8; nt++) {
            int col = n0 + (wnt + nt) * 8 + c * 2;
            if (row0 < count) {
                float2 o = { w0 * acc[mt][nt][0], w0 * acc[mt][nt][1] };
                *(float2*)(g_down + (size_t)(e * T + row0) * HDIM + col) = o;
            }
            if (row0 + 8 < count) {
                float2 o = { w1 * acc[mt][nt][2], w1 * acc[mt][nt][3] };
                *(float2*)(g_down + (size_t)(e * T + row0 + 8) * HDIM + col) = o;
            }
        }
    }
}

__global__ __launch_bounds__(128)
void shared_down_combine_tc(const float* __restrict__ wsd,
                            float* __restrict__ out) {
    int m0 = blockIdx.y * 64;
    int n0 = blockIdx.x * 128;

    __shared__ float As[2][1024];
    __shared__ float Bs[2][2048];

    int tid = threadIdx.x, lane = tid & 31, warp = tid >> 5;
    int wmt = (warp >> 1) * 2, wnt = (warp & 1) * 8;
    int r = lane >> 2, c = lane & 3;

    int ar = tid >> 1, ak = (tid & 1) * 8;
    int br = tid >> 3, bc = (tid & 7) * 16;

    const float* arow = g_acts + (size_t)(m0 + ar) * ISDIM;

    float4 pa0, pa1, pb[4];
    float acc[2][8][4] = {};

    DN_LD(wsd, HDIM, 0); DN_ST(0);
    const int NTILES = ISDIM / 16;
    for (int kt = 0; kt < NTILES; kt++) {
        __syncthreads();
        if (kt + 1 < NTILES) DN_LD(wsd, HDIM, (kt + 1) * 16);
        int b = kt & 1;
        #pragma unroll
        for (int kb = 0; kb < 2; kb++) {
            float4 afr[2];
            #pragma unroll
            for (int mt = 0; mt < 2; mt++)
                afr[mt] = *(const float4*)&As[b][((kb * 4 + wmt + mt) * 32 + lane) * 4];
            float2 bf[8];
            #pragma unroll
            for (int nt = 0; nt < 8; nt++)
                bf[nt] = *(const float2*)&Bs[b][((kb * 16 + wnt + nt) * 32 + lane) * 2];
            #pragma unroll
            for (int nt = 0; nt < 8; nt++)
                #pragma unroll
                for (int mt = 0; mt < 2; mt++)
                    mma_tf32(acc[mt][nt], (const float*)&afr[mt], (const float*)&bf[nt]);
        }
        if (kt + 1 < NTILES) DN_ST((kt + 1) & 1);
    }

    #pragma unroll
    for (int mt = 0; mt < 2; mt++) {
        #pragma unroll
        for (int half = 0; half < 2; half++) {
            int t = m0 + (wmt + mt) * 16 + r + half * 8;
            float sg = g_sg[t];
            int s0 = g_slot[t * TOPK + 0];
            int s1 = g_slot[t * TOPK + 1];
            int s2 = g_slot[t * TOPK + 2];
            int s3 = g_slot[t * TOPK + 3];
            #pragma unroll
            for (int nt = 0; nt < 8; nt++) {
                int col = n0 + (wnt + nt) * 8 + c * 2;
                float2 d0 = *(const float2*)(g_down + (size_t)s0 * HDIM + col);
                float2 d1 = *(const float2*)(g_down + (size_t)s1 * HDIM + col);
                float2 d2 = *(const float2*)(g_down + (size_t)s2 * HDIM + col);
                float2 d3 = *(const float2*)(g_down + (size_t)s3 * HDIM + col);
                float ax = acc[mt][nt][half * 2 + 0];
                float ay = acc[mt][nt][half * 2 + 1];
                float2 o;
                o.x = sg * ax + d0.x + d1.x + d2.x + d3.x;
                o.y = sg * ay + d0.y + d1.y + d2.y + d3.y;
                *(float2*)(out + (size_t)t * HDIM + col) = o;
            }
        }
    }
}

// ---------------- launch ----------------------------------------------------
extern "C" void kernel_launch(void* const* d_in, const int* in_sizes, int n_in,
                              void* d_out, int out_size) {
    const float* x    = (const float*)d_in[0];
    const float* wr   = (const float*)d_in[1];
    const float* wg   = (const float*)d_in[2];
    const float* wu   = (const float*)d_in[3];
    const float* wd   = (const float*)d_in[4];
    const float* wsg  = (const float*)d_in[5];
    const float* wsu  = (const float*)d_in[6];
    const float* wsd  = (const float*)d_in[7];
    const float* wshg = (const float*)d_in[8];
    float* out = (float*)d_out;

    zero_counts_kernel<<<1, 32>>>();
    router_kernel<<<T, 512>>>(x, wr, wshg, out + (size_t)T * HDIM);
    gateup_expert_tc<<<dim3(IDIM / 64, T / 64, NEXP), 128>>>(x, wg, wu);
    gateup_shared_tc<<<dim3(ISDIM / 64, T / 64), 128>>>(x, wsg, wsu);
    down_expert_tc<<<dim3(HDIM / 128, T / 64, NEXP), 128>>>(wd);
    shared_down_combine_tc<<<dim3(HDIM / 128, T / 64), 128>>>(wsd, out);
}

// round 5
// speedup vs baseline: 1.6078x; 1.6078x over previous
#include <cuda_runtime.h>
#include <cuda_bf16.h>
#include <math.h>

#define T     1024
#define HDIM  1024
#define NEXP  16
#define IDIM  512
#define ISDIM 2048
#define TOPK  4
#define SST   20          // smem row stride in floats (rows 16B-aligned, banks 20r mod 32 distinct)

// ---------------- scratch --------------------------------------------------
__device__ int   g_counts[NEXP];
__device__ int   g_tok[NEXP * T];
__device__ float g_wt[NEXP * T];
__device__ int   g_slot[T * TOPK];
__device__ float g_sg[T];
__device__ float g_act[(size_t)NEXP * T * IDIM];
__device__ float g_acts[(size_t)T * ISDIM];
__device__ float g_down[(size_t)NEXP * T * HDIM];

// ---------------- helpers --------------------------------------------------
__device__ __forceinline__ float to_tf32(float x) {
    unsigned u;
    asm("cvt.rna.tf32.f32 %0, %1;" : "=r"(u) : "f"(x));
    return __uint_as_float(u);
}
__device__ __forceinline__ float4 cvt4(float4 v) {
    v.x = to_tf32(v.x); v.y = to_tf32(v.y);
    v.z = to_tf32(v.z); v.w = to_tf32(v.w);
    return v;
}
__device__ __forceinline__ unsigned smem_u32(const void* p) {
    return (unsigned)__cvta_generic_to_shared(p);
}
__device__ __forceinline__ void ldsm4(unsigned* d, unsigned addr) {
    asm volatile("ldmatrix.sync.aligned.m8n8.x4.shared.b16 {%0,%1,%2,%3}, [%4];"
                 : "=r"(d[0]), "=r"(d[1]), "=r"(d[2]), "=r"(d[3]) : "r"(addr));
}
__device__ __forceinline__ void mma_tf32(float* d, const unsigned* a, const unsigned* b) {
    asm volatile(
        "mma.sync.aligned.m16n8k8.row.col.f32.tf32.tf32.f32 "
        "{%0,%1,%2,%3}, {%4,%5,%6,%7}, {%8,%9}, {%0,%1,%2,%3};\n"
        : "+f"(d[0]), "+f"(d[1]), "+f"(d[2]), "+f"(d[3])
        : "r"(a[0]), "r"(a[1]), "r"(a[2]), "r"(a[3]), "r"(b[0]), "r"(b[1]));
}
__device__ __forceinline__ float silu(float g) { return g / (1.f + expf(-g)); }

// ---------------- kernel 0 + 1: counts & router -----------------------------
__global__ void zero_counts_kernel() {
    if (threadIdx.x < NEXP) g_counts[threadIdx.x] = 0;
}

__global__ void router_kernel(const float* __restrict__ x,
                              const float* __restrict__ wr,
                              const float* __restrict__ wsg,
                              float* __restrict__ logits_out) {
    int t    = blockIdx.x;
    int warp = threadIdx.x >> 5;
    int lane = threadIdx.x & 31;
    __shared__ float s_logit[NEXP];

    const float* xr = x + (size_t)t * HDIM;
    {
        float acc = 0.f;
        for (int h = lane; h < HDIM; h += 32)
            acc += xr[h] * wr[h * NEXP + warp];
        #pragma unroll
        for (int o = 16; o; o >>= 1) acc += __shfl_xor_sync(0xffffffffu, acc, o);
        if (lane == 0) { s_logit[warp] = acc; logits_out[t * NEXP + warp] = acc; }
    }
    if (warp == 0) {
        float acc = 0.f;
        for (int h = lane; h < HDIM; h += 32) acc += xr[h] * wsg[h];
        #pragma unroll
        for (int o = 16; o; o >>= 1) acc += __shfl_xor_sync(0xffffffffu, acc, o);
        if (lane == 0) g_sg[t] = 1.f / (1.f + expf(-acc));
    }
    __syncthreads();

    if (threadIdx.x == 0) {
        float p[NEXP];
        float mx = -1e30f;
        #pragma unroll
        for (int e = 0; e < NEXP; e++) mx = fmaxf(mx, s_logit[e]);
        float sum = 0.f;
        #pragma unroll
        for (int e = 0; e < NEXP; e++) { p[e] = expf(s_logit[e] - mx); sum += p[e]; }
        float inv = 1.f / sum;
        #pragma unroll
        for (int e = 0; e < NEXP; e++) p[e] *= inv;

        int idx[TOPK]; float w[TOPK]; float wsum = 0.f;
        #pragma unroll
        for (int k = 0; k < TOPK; k++) {
            int best = 0; float bv = -1.f;
            #pragma unroll
            for (int e = 0; e < NEXP; e++)
                if (p[e] > bv) { bv = p[e]; best = e; }
            idx[k] = best; w[k] = bv; wsum += bv; p[best] = -2.f;
        }
        float winv = 1.f / wsum;
        #pragma unroll
        for (int k = 0; k < TOPK; k++) {
            int e = idx[k];
            int pos = atomicAdd(&g_counts[e], 1);
            g_tok[e * T + pos] = t;
            g_wt[e * T + pos]  = w[k] * winv;
            g_slot[t * TOPK + k] = e * T + pos;
        }
    }
}

// ============================================================================
// gate/up: BM=64, BN=64, BK=16, 128 thr, warps 2x2 (warp 32x32).
// A row-major [m][SST]; B stored TRANSPOSED [n][SST]; fragments via ldmatrix.
// ============================================================================
__global__ __launch_bounds__(128)
void gateup_expert_tc(const float* __restrict__ x,
                      const float* __restrict__ wg,
                      const float* __restrict__ wu) {
    int e     = blockIdx.z;
    int count = g_counts[e];
    int m0    = blockIdx.y * 64;
    if (m0 >= count) return;
    int n0 = blockIdx.x * 64;

    const float* Bgp = wg + (size_t)e * HDIM * IDIM;
    const float* Bup = wu + (size_t)e * HDIM * IDIM;

    __shared__ float As [2][64][SST];
    __shared__ float Btg[2][64][SST];
    __shared__ float Btu[2][64][SST];

    int tid = threadIdx.x, lane = tid & 31, warp = tid >> 5;
    int wm = (warp >> 1) * 32, wn = (warp & 1) * 32;
    int r = lane >> 2, c = lane & 3;

    // ldmatrix lane address offsets (floats)
    int aoff = (wm + (lane & 7) + ((lane >> 3) & 1) * 8) * SST + ((lane >> 4) & 1) * 4;
    unsigned aA0 = smem_u32(&As[0][0][0]) + (unsigned)aoff * 4;          // mt=0
    int boff0 = (wn + (lane & 7) + ((lane >> 4) & 1) * 8) * SST + ((lane >> 3) & 1) * 4;
    unsigned aBg0 = smem_u32(&Btg[0][0][0]) + (unsigned)boff0 * 4;       // p=0
    unsigned aBu0 = smem_u32(&Btu[0][0][0]) + (unsigned)boff0 * 4;
    const unsigned BUFB = 64 * SST * 4;

    // loaders
    int arl = tid & 63, akf = (tid >> 6) * 8;     // A: row, k-offset
    int bnl = tid & 63, bkf = (tid >> 6) * 8;     // B: n, k-offset

    int row = m0 + arl;
    const float* arow = (row < count) ? (x + (size_t)g_tok[e * T + row] * HDIM)
                                      : nullptr;

    float4 pa0, pa1;
    float pg[8], pu[8];
    #define GU_LD(K0) do {                                                     \
        pa0 = arow ? *(const float4*)(arow + (K0) + akf) : make_float4(0,0,0,0);\
        pa1 = arow ? *(const float4*)(arow + (K0) + akf + 4) : make_float4(0,0,0,0);\
        _Pragma("unroll")                                                      \
        for (int j = 0; j < 8; j++) {                                          \
            pg[j] = Bgp[(size_t)((K0) + bkf + j) * IDIM + n0 + bnl];           \
            pu[j] = Bup[(size_t)((K0) + bkf + j) * IDIM + n0 + bnl];           \
        }                                                                      \
    } while (0)
    #define GU_ST(B) do {                                                      \
        *(float4*)&As[B][arl][akf]     = cvt4(pa0);                            \
        *(float4*)&As[B][arl][akf + 4] = cvt4(pa1);                            \
        *(float4*)&Btg[B][bnl][bkf]     = cvt4(make_float4(pg[0],pg[1],pg[2],pg[3])); \
        *(float4*)&Btg[B][bnl][bkf + 4] = cvt4(make_float4(pg[4],pg[5],pg[6],pg[7])); \
        *(float4*)&Btu[B][bnl][bkf]     = cvt4(make_float4(pu[0],pu[1],pu[2],pu[3])); \
        *(float4*)&Btu[B][bnl][bkf + 4] = cvt4(make_float4(pu[4],pu[5],pu[6],pu[7])); \
    } while (0)

    float ag[2][4][4] = {};
    float au[2][4][4] = {};

    GU_LD(0); GU_ST(0);
    const int NTILES = HDIM / 16;
    for (int kt = 0; kt < NTILES; kt++) {
        __syncthreads();
        if (kt + 1 < NTILES) GU_LD((kt + 1) * 16);
        unsigned bsel = (kt & 1) * BUFB;
        #pragma unroll
        for (int kb = 0; kb < 2; kb++) {
            unsigned koff = bsel + kb * 32;
            unsigned af[2][4], bgf[2][4], buf_[2][4];
            ldsm4(af[0], aA0 + koff);
            ldsm4(af[1], aA0 + koff + 16 * SST * 4);
            ldsm4(bgf[0], aBg0 + koff);
            ldsm4(bgf[1], aBg0 + koff + 16 * SST * 4);
            ldsm4(buf_[0], aBu0 + koff);
            ldsm4(buf_[1], aBu0 + koff + 16 * SST * 4);
            #pragma unroll
            for (int nt = 0; nt < 4; nt++) {
                const unsigned* bg = &bgf[nt >> 1][(nt & 1) * 2];
                const unsigned* bu = &buf_[nt >> 1][(nt & 1) * 2];
                #pragma unroll
                for (int mt = 0; mt < 2; mt++) {
                    mma_tf32(ag[mt][nt], af[mt], bg);
                    mma_tf32(au[mt][nt], af[mt], bu);
                }
            }
        }
        if (kt + 1 < NTILES) GU_ST((kt + 1) & 1);
    }

    float* Cb = g_act + (size_t)e * T * IDIM;
    #pragma unroll
    for (int mt = 0; mt < 2; mt++) {
        int row0 = m0 + wm + mt * 16 + r;
        #pragma unroll
        for (int nt = 0; nt < 4; nt++) {
            int col = n0 + wn + nt * 8 + c * 2;
            if (row0 < count) {
                float2 o = { silu(ag[mt][nt][0]) * au[mt][nt][0],
                             silu(ag[mt][nt][1]) * au[mt][nt][1] };
                *(float2*)(Cb + (size_t)row0 * IDIM + col) = o;
            }
            if (row0 + 8 < count) {
                float2 o = { silu(ag[mt][nt][2]) * au[mt][nt][2],
                             silu(ag[mt][nt][3]) * au[mt][nt][3] };
                *(float2*)(Cb + (size_t)(row0 + 8) * IDIM + col) = o;
            }
        }
    }
}

__global__ __launch_bounds__(128)
void gateup_shared_tc(const float* __restrict__ x,
                      const float* __restrict__ wsg,
                      const float* __restrict__ wsu) {
    int m0 = blockIdx.y * 64;
    int n0 = blockIdx.x * 64;

    __shared__ float As [2][64][SST];
    __shared__ float Btg[2][64][SST];
    __shared__ float Btu[2][64][SST];

    int tid = threadIdx.x, lane = tid & 31, warp = tid >> 5;
    int wm = (warp >> 1) * 32, wn = (warp & 1) * 32;
    int r = lane >> 2, c = lane & 3;

    int aoff = (wm + (lane & 7) + ((lane >> 3) & 1) * 8) * SST + ((lane >> 4) & 1) * 4;
    unsigned aA0 = smem_u32(&As[0][0][0]) + (unsigned)aoff * 4;
    int boff0 = (wn + (lane & 7) + ((lane >> 4) & 1) * 8) * SST + ((lane >> 3) & 1) * 4;
    unsigned aBg0 = smem_u32(&Btg[0][0][0]) + (unsigned)boff0 * 4;
    unsigned aBu0 = smem_u32(&Btu[0][0][0]) + (unsigned)boff0 * 4;
    const unsigned BUFB = 64 * SST * 4;

    int arl = tid & 63, akf = (tid >> 6) * 8;
    int bnl = tid & 63, bkf = (tid >> 6) * 8;

    const float* arow = x + (size_t)(m0 + arl) * HDIM;

    float4 pa0, pa1;
    float pg[8], pu[8];
    #define GS_LD(K0) do {                                                     \
        pa0 = *(const float4*)(arow + (K0) + akf);                             \
        pa1 = *(const float4*)(arow + (K0) + akf + 4);                         \
        _Pragma("unroll")                                                      \
        for (int j = 0; j < 8; j++) {                                          \
            pg[j] = wsg[(size_t)((K0) + bkf + j) * ISDIM + n0 + bnl];          \
            pu[j] = wsu[(size_t)((K0) + bkf + j) * ISDIM + n0 + bnl];          \
        }                                                                      \
    } while (0)

    float ag[2][4][4] = {};
    float au[2][4][4] = {};

    GS_LD(0); GU_ST(0);
    const int NTILES = HDIM / 16;
    for (int kt = 0; kt < NTILES; kt++) {
        __syncthreads();
        if (kt + 1 < NTILES) GS_LD((kt + 1) * 16);
        unsigned bsel = (kt & 1) * BUFB;
        #pragma unroll
        for (int kb = 0; kb < 2; kb++) {
            unsigned koff = bsel + kb * 32;
            unsigned af[2][4], bgf[2][4], buf_[2][4];
            ldsm4(af[0], aA0 + koff);
            ldsm4(af[1], aA0 + koff + 16 * SST * 4);
            ldsm4(bgf[0], aBg0 + koff);
            ldsm4(bgf[1], aBg0 + koff + 16 * SST * 4);
            ldsm4(buf_[0], aBu0 + koff);
            ldsm4(buf_[1], aBu0 + koff + 16 * SST * 4);
            #pragma unroll
            for (int nt = 0; nt < 4; nt++) {
                const unsigned* bg = &bgf[nt >> 1][(nt & 1) * 2];
                const unsigned* bu = &buf_[nt >> 1][(nt & 1) * 2];
                #pragma unroll
                for (int mt = 0; mt < 2; mt++) {
                    mma_tf32(ag[mt][nt], af[mt], bg);
                    mma_tf32(au[mt][nt], af[mt], bu);
                }
            }
        }
        if (kt + 1 < NTILES) GU_ST((kt + 1) & 1);
    }

    #pragma unroll
    for (int mt = 0; mt < 2; mt++) {
        int row0 = m0 + wm + mt * 16 + r;
        #pragma unroll
        for (int nt = 0; nt < 4; nt++) {
            int col = n0 + wn + nt * 8 + c * 2;
            float2 o0 = { silu(ag[mt][nt][0]) * au[mt][nt][0],
                          silu(ag[mt][nt][1]) * au[mt][nt][1] };
            float2 o1 = { silu(ag[mt][nt][2]) * au[mt][nt][2],
                          silu(ag[mt][nt][3]) * au[mt][nt][3] };
            *(float2*)(g_acts + (size_t)row0 * ISDIM + col)       = o0;
            *(float2*)(g_acts + (size_t)(row0 + 8) * ISDIM + col) = o1;
        }
    }
}

// ============================================================================
// down: BM=64, BN=128, BK=16, 128 thr, warps 2x2 (warp 32x64).
// ============================================================================
__global__ __launch_bounds__(128)
void down_expert_tc(const float* __restrict__ wd) {
    int e     = blockIdx.z;
    int count = g_counts[e];
    int m0    = blockIdx.y * 64;
    if (m0 >= count) return;
    int n0 = blockIdx.x * 128;

    const float* A = g_act + (size_t)e * T * IDIM;
    const float* B = wd    + (size_t)e * IDIM * HDIM;

    __shared__ float As[2][64][SST];
    __shared__ float Bt[2][128][SST];

    int tid = threadIdx.x, lane = tid & 31, warp = tid >> 5;
    int wm = (warp >> 1) * 32, wn = (warp & 1) * 64;
    int r = lane >> 2, c = lane & 3;

    int aoff = (wm + (lane & 7) + ((lane >> 3) & 1) * 8) * SST + ((lane >> 4) & 1) * 4;
    unsigned aA0 = smem_u32(&As[0][0][0]) + (unsigned)aoff * 4;
    int boff0 = (wn + (lane & 7) + ((lane >> 4) & 1) * 8) * SST + ((lane >> 3) & 1) * 4;
    unsigned aB0 = smem_u32(&Bt[0][0][0]) + (unsigned)boff0 * 4;
    const unsigned ABUF = 64 * SST * 4, BBUF = 128 * SST * 4;

    int arl = tid & 63, akf = (tid >> 6) * 8;
    int bnl = tid;                                  // n = 0..127, all 16 k's

    const float* arow = A + (size_t)(m0 + arl) * IDIM;

    float4 pa0, pa1;
    float pb[16];
    #define DN_LD(BP, LDB, K0) do {                                            \
        pa0 = *(const float4*)(arow + (K0) + akf);                             \
        pa1 = *(const float4*)(arow + (K0) + akf + 4);                         \
        _Pragma("unroll")                                                      \
        for (int j = 0; j < 16; j++)                                           \
            pb[j] = (BP)[(size_t)((K0) + j) * (LDB) + n0 + bnl];               \
    } while (0)
    #define DN_ST(BUF) do {                                                    \
        *(float4*)&As[BUF][arl][akf]     = cvt4(pa0);                          \
        *(float4*)&As[BUF][arl][akf + 4] = cvt4(pa1);                          \
        _Pragma("unroll")                                                      \
        for (int q = 0; q < 4; q++)                                            \
            *(float4*)&Bt[BUF][bnl][q * 4] =                                   \
                cvt4(make_float4(pb[q*4], pb[q*4+1], pb[q*4+2], pb[q*4+3]));   \
    } while (0)

    float acc[2][8][4] = {};

    DN_LD(B, HDIM, 0); DN_ST(0);
    const int NTILES = IDIM / 16;
    for (int kt = 0; kt < NTILES; kt++) {
        __syncthreads();
        if (kt + 1 < NTILES) DN_LD(B, HDIM, (kt + 1) * 16);
        unsigned bselA = (kt & 1) * ABUF, bselB = (kt & 1) * BBUF;
        #pragma unroll
        for (int kb = 0; kb < 2; kb++) {
            unsigned af[2][4], bf[4][4];
            ldsm4(af[0], aA0 + bselA + kb * 32);
            ldsm4(af[1], aA0 + bselA + kb * 32 + 16 * SST * 4);
            #pragma unroll
            for (int p = 0; p < 4; p++)
                ldsm4(bf[p], aB0 + bselB + kb * 32 + p * 16 * SST * 4);
            #pragma unroll
            for (int nt = 0; nt < 8; nt++) {
                const unsigned* b = &bf[nt >> 1][(nt & 1) * 2];
                #pragma unroll
                for (int mt = 0; mt < 2; mt++)
                    mma_tf32(acc[mt][nt], af[mt], b);
            }
        }
        if (kt + 1 < NTILES) DN_ST((kt + 1) & 1);
    }

    #pragma unroll
    for (int mt = 0; mt < 2; mt++) {
        int row0 = m0 + wm + mt * 16 + r;
        float w0 = (row0 < count)     ? g_wt[e * T + row0]     : 0.f;
        float w1 = (row0 + 8 < count) ? g_wt[e * T + row0 + 8] : 0.f;
        #pragma unroll
        for (int nt = 0; nt < 8; nt++) {
            int col = n0 + wn + nt * 8 + c * 2;
            if (row0 < count) {
                float2 o = { w0 * acc[mt][nt][0], w0 * acc[mt][nt][1] };
                *(float2*)(g_down + (size_t)(e * T + row0) * HDIM + col) = o;
            }
            if (row0 + 8 < count) {
                float2 o = { w1 * acc[mt][nt][2], w1 * acc[mt][nt][3] };
                *(float2*)(g_down + (size_t)(e * T + row0 + 8) * HDIM + col) = o;
            }
        }
    }
}

__global__ __launch_bounds__(128)
void shared_down_combine_tc(const float* __restrict__ wsd,
                            float* __restrict__ out) {
    int m0 = blockIdx.y * 64;
    int n0 = blockIdx.x * 128;

    __shared__ float As[2][64][SST];
    __shared__ float Bt[2][128][SST];

    int tid = threadIdx.x, lane = tid & 31, warp = tid >> 5;
    int wm = (warp >> 1) * 32, wn = (warp & 1) * 64;
    int r = lane >> 2, c = lane & 3;

    int aoff = (wm + (lane & 7) + ((lane >> 3) & 1) * 8) * SST + ((lane >> 4) & 1) * 4;
    unsigned aA0 = smem_u32(&As[0][0][0]) + (unsigned)aoff * 4;
    int boff0 = (wn + (lane & 7) + ((lane >> 4) & 1) * 8) * SST + ((lane >> 3) & 1) * 4;
    unsigned aB0 = smem_u32(&Bt[0][0][0]) + (unsigned)boff0 * 4;
    const unsigned ABUF = 64 * SST * 4, BBUF = 128 * SST * 4;

    int arl = tid & 63, akf = (tid >> 6) * 8;
    int bnl = tid;

    const float* arow = g_acts + (size_t)(m0 + arl) * ISDIM;

    float4 pa0, pa1;
    float pb[16];
    float acc[2][8][4] = {};

    DN_LD(wsd, HDIM, 0); DN_ST(0);
    const int NTILES = ISDIM / 16;
    for (int kt = 0; kt < NTILES; kt++) {
        __syncthreads();
        if (kt + 1 < NTILES) DN_LD(wsd, HDIM, (kt + 1) * 16);
        unsigned bselA = (kt & 1) * ABUF, bselB = (kt & 1) * BBUF;
        #pragma unroll
        for (int kb = 0; kb < 2; kb++) {
            unsigned af[2][4], bf[4][4];
            ldsm4(af[0], aA0 + bselA + kb * 32);
            ldsm4(af[1], aA0 + bselA + kb * 32 + 16 * SST * 4);
            #pragma unroll
            for (int p = 0; p < 4; p++)
                ldsm4(bf[p], aB0 + bselB + kb * 32 + p * 16 * SST * 4);
            #pragma unroll
            for (int nt = 0; nt < 8; nt++) {
                const unsigned* b = &bf[nt >> 1][(nt & 1) * 2];
                #pragma unroll
                for (int mt = 0; mt < 2; mt++)
                    mma_tf32(acc[mt][nt], af[mt], b);
            }
        }
        if (kt + 1 < NTILES) DN_ST((kt + 1) & 1);
    }

    #pragma unroll
    for (int mt = 0; mt < 2; mt++) {
        #pragma unroll
        for (int half = 0; half < 2; half++) {
            int t = m0 + wm + mt * 16 + r + half * 8;
            float sg = g_sg[t];
            int s0 = g_slot[t * TOPK + 0];
            int s1 = g_slot[t * TOPK + 1];
            int s2 = g_slot[t * TOPK + 2];
            int s3 = g_slot[t * TOPK + 3];
            #pragma unroll
            for (int nt = 0; nt < 8; nt++) {
                int col = n0 + wn + nt * 8 + c * 2;
                float2 d0 = *(const float2*)(g_down + (size_t)s0 * HDIM + col);
                float2 d1 = *(const float2*)(g_down + (size_t)s1 * HDIM + col);
                float2 d2 = *(const float2*)(g_down + (size_t)s2 * HDIM + col);
                float2 d3 = *(const float2*)(g_down + (size_t)s3 * HDIM + col);
                float ax = acc[mt][nt][half * 2 + 0];
                float ay = acc[mt][nt][half * 2 + 1];
                float2 o;
                o.x = sg * ax + d0.x + d1.x + d2.x + d3.x;
                o.y = sg * ay + d0.y + d1.y + d2.y + d3.y;
                *(float2*)(out + (size_t)t * HDIM + col) = o;
            }
        }
    }
}

// ---------------- launch ----------------------------------------------------
extern "C" void kernel_launch(void* const* d_in, const int* in_sizes, int n_in,
                              void* d_out, int out_size) {
    const float* x    = (const float*)d_in[0];
    const float* wr   = (const float*)d_in[1];
    const float* wg   = (const float*)d_in[2];
    const float* wu   = (const float*)d_in[3];
    const float* wd   = (const float*)d_in[4];
    const float* wsg  = (const float*)d_in[5];
    const float* wsu  = (const float*)d_in[6];
    const float* wsd  = (const float*)d_in[7];
    const float* wshg = (const float*)d_in[8];
    float* out = (float*)d_out;

    zero_counts_kernel<<<1, 32>>>();
    router_kernel<<<T, 512>>>(x, wr, wshg, out + (size_t)T * HDIM);
    gateup_expert_tc<<<dim3(IDIM / 64, T / 64, NEXP), 128>>>(x, wg, wu);
    gateup_shared_tc<<<dim3(ISDIM / 64, T / 64), 128>>>(x, wsg, wsu);
    down_expert_tc<<<dim3(HDIM / 128, T / 64, NEXP), 128>>>(wd);
    shared_down_combine_tc<<<dim3(HDIM / 128, T / 64), 128>>>(wsd, out);
}